// round 11
// baseline (speedup 1.0000x reference)
#include <cuda_runtime.h>

// ============================================================================
// AdderNet TauNet R11: R10 (pair-per-warp E=2 end-to-end) with workspace
// stride padded to 16B multiple (WS_N 1282 -> 1284) -- fixes misaligned float4.
// ============================================================================

#define EPSV 1e-5f

// ---- s_small layout (floats), compact ----
#define W1OFF   0      // 5 x 16
#define W2OFF   80     // 50 x 12
#define R1TOFF  680    // 10ci x 16  (transposed: [ci][8g + j] = w[5g+j][ci])
#define R2TOFF  840    // 10ci x 16
#define A1OFF   1000
#define B1OFF   1005
#define A2OFF   1010
#define B2OFF   1020
#define AR1OFF  1030
#define BR1OFF  1040
#define AR2OFF  1050
#define BR2OFF  1060
#define AOAOFF  1070   // 140
#define BOAOFF  1210   // 140
#define AOBOFF  1350   // 60
#define BOBOFF  1410   // 60
#define AOCOFF  1470   // 2
#define BOCOFF  1472   // 2
#define QOCOFF  1474   // 64
#define SMALL_N 1540

__device__ float g_small[1544];
__device__ float g_qoa[2 * 35 * 70 * 4];   // [branch][i/4][c][4]
__device__ float g_qob[2 * 18 * 30 * 4];

__device__ __forceinline__ float quantv(float w, float s) {
    float t = fminf(fmaxf(w / s, -127.f), 127.f);
    return rintf(t) * s;
}

__device__ __forceinline__ void fill_bn(const float* bn, int c, float* A, float* Bt) {
    for (int i = threadIdx.x; i < c; i += blockDim.x) {
        float g = bn[i], b = bn[c + i], m = bn[2 * c + i], v = bn[3 * c + i];
        float al = g * rsqrtf(v + EPSV);
        A[i] = al;
        Bt[i] = b - m * al;
    }
}

// ---------------------------------------------------------------------------
__global__ void setup_kernel(
    const float* __restrict__ w1,   const float* __restrict__ w2,
    const float* __restrict__ wr1,  const float* __restrict__ wr2,
    const float* __restrict__ wo1a, const float* __restrict__ wo1b, const float* __restrict__ wo1c,
    const float* __restrict__ wo2a, const float* __restrict__ wo2b, const float* __restrict__ wo2c,
    const float* __restrict__ bn1,  const float* __restrict__ bn2,
    const float* __restrict__ bnr1, const float* __restrict__ bnr2,
    const float* __restrict__ bno1a, const float* __restrict__ bno1b, const float* __restrict__ bno1c,
    const float* __restrict__ bno2a, const float* __restrict__ bno2b, const float* __restrict__ bno2c)
{
    const int blk = blockIdx.x, tid = threadIdx.x;
    if (blk < 10) {
        const float* w; int n;
        switch (blk) {
            case 0: w = w1;   n = 65;   break;
            case 1: w = w2;   n = 450;  break;
            case 2: w = wr1;  n = 100;  break;
            case 3: w = wr2;  n = 100;  break;
            case 4: w = wo1a; n = 9800; break;
            case 5: w = wo2a; n = 9800; break;
            case 6: w = wo1b; n = 2100; break;
            case 7: w = wo2b; n = 2100; break;
            case 8: w = wo1c; n = 30;   break;
            default: w = wo2c; n = 30;  break;
        }
        __shared__ float red[256];
        float m = 0.f;
        for (int i = tid; i < n; i += 256) m = fmaxf(m, fabsf(w[i]));
        red[tid] = m;
        __syncthreads();
        for (int s = 128; s > 0; s >>= 1) {
            if (tid < s) red[tid] = fmaxf(red[tid], red[tid + s]);
            __syncthreads();
        }
        const float s = red[0] / 127.f;

        if (blk == 0) {
            for (int j = tid; j < 80; j += 256) {
                int c = j >> 4, k = j & 15;
                g_small[W1OFF + j] = (k < 13) ? quantv(w[c * 13 + k], s) : 0.f;
            }
        } else if (blk == 1) {
            for (int j = tid; j < 600; j += 256) {
                int row = j / 12, k = j - row * 12;
                g_small[W2OFF + j] = (k < 9) ? quantv(w[row * 9 + k], s) : 0.f;
            }
        } else if (blk == 2 || blk == 3) {
            // transposed: dst[ci*16 + 8g + k] = quant(w[(5g+k)*10 + ci]), k<5
            float* dst = g_small + (blk == 2 ? R1TOFF : R2TOFF);
            for (int j = tid; j < 160; j += 256) {
                int ci = j >> 4, rem = j & 15;
                int g = rem >> 3, k = rem & 7;
                int c = 5 * g + k;
                dst[j] = (k < 5) ? quantv(w[c * 10 + ci], s) : 0.f;
            }
        } else if (blk == 4 || blk == 5) {
            float* dst = g_qoa + (blk - 4) * 9800;
            for (int j = tid; j < 9800; j += 256) {
                int i4 = j / 280, rem = j - i4 * 280;
                int c = rem >> 2, t = rem & 3;
                dst[j] = quantv(w[c * 140 + i4 * 4 + t], s);
            }
        } else if (blk == 6 || blk == 7) {
            float* dst = g_qob + (blk - 6) * 2160;
            for (int j = tid; j < 2160; j += 256) {
                int i4 = j / 120, rem = j - i4 * 120;
                int c = rem >> 2, t = rem & 3;
                int i = i4 * 4 + t;
                dst[j] = (i < 70) ? quantv(w[c * 70 + i], s) : 0.f;
            }
        } else {
            float* dst = g_small + QOCOFF + (blk - 8) * 32;
            if (tid < 32) dst[tid] = (tid < 30) ? quantv(w[tid], s) : 0.f;
        }
    } else {
        fill_bn(bn1, 5,  g_small + A1OFF,  g_small + B1OFF);
        fill_bn(bn2, 10, g_small + A2OFF,  g_small + B2OFF);
        fill_bn(bnr1, 10, g_small + AR1OFF, g_small + BR1OFF);
        fill_bn(bnr2, 10, g_small + AR2OFF, g_small + BR2OFF);
        fill_bn(bno1a, 70, g_small + AOAOFF,      g_small + BOAOFF);
        fill_bn(bno2a, 70, g_small + AOAOFF + 70, g_small + BOAOFF + 70);
        fill_bn(bno1b, 30, g_small + AOBOFF,      g_small + BOBOFF);
        fill_bn(bno2b, 30, g_small + AOBOFF + 30, g_small + BOBOFF + 30);
        fill_bn(bno1c, 1, g_small + AOCOFF,     g_small + BOCOFF);
        fill_bn(bno2c, 1, g_small + AOCOFF + 1, g_small + BOCOFF + 1);
    }
}

// ---------------------------------------------------------------------------
// Per-warp workspace (floats). Activations float2 = (e0,e1).
//   X  @0     float2[256] (512)   [T aliases X; A aliases X]
//   H1 @512   float2[245] (490)   stride-49 rows  [F aliases H1]
//   H2 @1002  float2[140] (280)   [B aliases H2]
// WS_N padded to multiple of 4 floats so every warp's base is 16B-aligned.
#define XOFF  0
#define H1OFF 512
#define H2OFF 1002
#define FOFF  512
#define AOFF  0
#define BOFF  1002
#define WS_N  1284

__device__ __forceinline__ void ld4(float* d, const float* s) {
    float4 v = *(const float4*)s;
    d[0] = v.x; d[1] = v.y; d[2] = v.z; d[3] = v.w;
}

// d = u - w as FFMA-imm (bit-identical)
__device__ __forceinline__ float fdiff(float u, float w) {
    float d;
    asm("fma.rn.f32 %0, %1, 0fBF800000, %2;" : "=f"(d) : "f"(w), "f"(u));
    return d;
}

// acc[e] += |u[e] - w| over 2 packed elements
__device__ __forceinline__ void acc2(float2& a, float2 u, float w) {
    a.x += fabsf(fdiff(u.x, w));
    a.y += fabsf(fdiff(u.y, w));
}

__device__ __forceinline__ float2 add2(float2 a, float2 b) {
    return make_float2(a.x + b.x, a.y + b.y);
}

__device__ __forceinline__ float2 bnrelu2(float2 a, float al, float be) {
    return make_float2(fmaxf(fmaf(-a.x, al, be), 0.f),
                       fmaxf(fmaf(-a.y, al, be), 0.f));
}

#define ZERO2 make_float2(0.f, 0.f)

__global__ void __launch_bounds__(256) taunet_main(const float* __restrict__ x,
                                                   float* __restrict__ out, int nB)
{
    __shared__ __align__(16) float s_small[SMALL_N];
    __shared__ __align__(16) float s_ws[8][WS_N];

    for (int i = threadIdx.x; i < SMALL_N; i += 256) s_small[i] = g_small[i];
    __syncthreads();

    const int warp = threadIdx.x >> 5, lane = threadIdx.x & 31;
    float* ws = s_ws[warp];
    float2* X2  = (float2*)(ws + XOFF);
    float2* H12 = (float2*)(ws + H1OFF);
    float2* H22 = (float2*)(ws + H2OFF);
    float2* T2  = (float2*)(ws + XOFF);
    float2* F2  = (float2*)(ws + FOFF);
    float2* A2  = (float2*)(ws + AOFF);
    float2* B2  = (float2*)(ws + BOFF);

    // ---- per-lane o-layer slot precompute ----
    const int j2 = lane + 64, j3 = lane + 96;
    const int j4 = (lane + 128 < 140) ? lane + 128 : 139;
    const int oa2 = (j2 < 70) ? j2 : (2450 + (j2 - 70));
    const int oa3 = 2450 + (j3 - 70);
    const int oa4 = 2450 + (j4 - 70);
    const int d2 = (j2 < 70) ? j2 : (72 + (j2 - 70));
    const int d3 = 72 + (j3 - 70);
    const int d4 = 72 + (j4 - 70);
    const int jb1 = (lane + 32 < 60) ? lane + 32 : 59;
    const int obb0 = lane / 30, obc0 = lane - 30 * obb0;
    const int ob0 = obb0 * 540 + obc0;
    const int ob1 = 540 + (jb1 - 30);
    // r1/r2 mapping: lanes 0..27 -> (p, g)
    const int rp = lane >> 1, rg = lane & 1;

    const int nP = (nB + 1) >> 1;
    const int gw = blockIdx.x * 8 + warp;
    const int stride = gridDim.x * 8;

    for (int p = gw; p < nP; p += stride) {
        const int e0 = 2 * p;
        const int e1r = 2 * p + 1;
        const bool e1ok = (e1r < nB);
        const int e1 = e1ok ? e1r : e0;

        // ---- stage 2 input rows, transposed into float2-per-position ----
        {
            const float4* r0 = (const float4*)(x + (size_t)e0 * 256);
            const float4* r1 = (const float4*)(x + (size_t)e1 * 256);
            float4* X4v = (float4*)X2;
            #pragma unroll
            for (int i = 0; i < 2; i++) {
                int m = lane + 32 * i;
                float4 a = __ldg(r0 + m);
                float4 b = __ldg(r1 + m);
                X4v[2 * m]     = make_float4(a.x, b.x, a.y, b.y);
                X4v[2 * m + 1] = make_float4(a.z, b.z, a.w, b.w);
            }
        }
        __syncwarp();

        // ---- pre1: 125 dual-position tasks (5ch x 25pd), K=13, stride 5 ----
        #pragma unroll 1
        for (int r = 0; r < 4; r++) {
            int idx = lane + 32 * r;
            if (idx < 125) {
                int c = idx / 25, pd = idx - 25 * c;
                int p0 = 2 * pd;
                bool dual = (pd < 24);
                float w[16];
                const float* wb = s_small + W1OFF + c * 16;
                ld4(w, wb); ld4(w + 4, wb + 4); ld4(w + 8, wb + 8); ld4(w + 12, wb + 12);
                const float2* xp = X2 + 5 * p0;
                float2 A0 = ZERO2, B0 = ZERO2, A1 = ZERO2, B1 = ZERO2;
                #pragma unroll
                for (int k = 0; k < 13; k++) {
                    float2 a = xp[k];
                    if (k & 1) acc2(B0, a, w[k]); else acc2(A0, a, w[k]);
                    if (k >= 5) {
                        if ((k - 5) & 1) acc2(B1, a, w[k - 5]); else acc2(A1, a, w[k - 5]);
                    }
                }
                if (dual) {
                    #pragma unroll
                    for (int k = 13; k < 18; k++) {
                        float2 a = xp[k];
                        if ((k - 5) & 1) acc2(B1, a, w[k - 5]); else acc2(A1, a, w[k - 5]);
                    }
                }
                float al = s_small[A1OFF + c], be = s_small[B1OFF + c];
                H12[c * 49 + p0] = bnrelu2(add2(A0, B0), al, be);
                if (dual)
                    H12[c * 49 + p0 + 1] = bnrelu2(add2(A1, B1), al, be);
            }
        }
        __syncwarp();

        // ---- pre2: 140 tasks (10ch x 14pos), 5cin x K=9, stride 3 ----
        #pragma unroll 1
        for (int r = 0; r < 5; r++) {
            int idx = lane + 32 * r;
            if (idx < 140) {
                int c = idx / 14, pp = idx - 14 * c;
                const float2* hp = H12 + 3 * pp;
                float2 Aa = ZERO2, Bb = ZERO2;
                #pragma unroll
                for (int ci = 0; ci < 5; ci++) {
                    float w[12];
                    const float* wb = s_small + W2OFF + (c * 5 + ci) * 12;
                    ld4(w, wb); ld4(w + 4, wb + 4); ld4(w + 8, wb + 8);
                    const float2* hc = hp + ci * 49;
                    #pragma unroll
                    for (int k = 0; k < 9; k++) {
                        if (k & 1) acc2(Bb, hc[k], w[k]); else acc2(Aa, hc[k], w[k]);
                    }
                }
                H22[c * 14 + pp] = bnrelu2(add2(Aa, Bb), s_small[A2OFF + c], s_small[B2OFF + c]);
            }
        }
        __syncwarp();

        // ---- r1: position-major, lanes 0..27 = (p, g); 5 channels each ----
        if (lane < 28) {
            float2 acc[5];
            #pragma unroll
            for (int j = 0; j < 5; j++) acc[j] = ZERO2;
            const float* wt = s_small + R1TOFF + 8 * rg;
            #pragma unroll
            for (int ci = 0; ci < 10; ci++) {
                float2 a = H22[ci * 14 + rp];
                float w8[8];
                ld4(w8, wt + ci * 16); ld4(w8 + 4, wt + ci * 16 + 4);
                #pragma unroll
                for (int j = 0; j < 5; j++) acc2(acc[j], a, w8[j]);
            }
            #pragma unroll
            for (int j = 0; j < 5; j++) {
                int c = 5 * rg + j;
                T2[c * 14 + rp] = bnrelu2(acc[j], s_small[AR1OFF + c], s_small[BR1OFF + c]);
            }
        }
        __syncwarp();

        // ---- r2 + residual: same mapping, F over dead H1 ----
        if (lane < 28) {
            float2 acc[5];
            #pragma unroll
            for (int j = 0; j < 5; j++) acc[j] = ZERO2;
            const float* wt = s_small + R2TOFF + 8 * rg;
            #pragma unroll
            for (int ci = 0; ci < 10; ci++) {
                float2 a = T2[ci * 14 + rp];
                float w8[8];
                ld4(w8, wt + ci * 16); ld4(w8 + 4, wt + ci * 16 + 4);
                #pragma unroll
                for (int j = 0; j < 5; j++) acc2(acc[j], a, w8[j]);
            }
            #pragma unroll
            for (int j = 0; j < 5; j++) {
                int c = 5 * rg + j;
                float al = s_small[AR2OFF + c], be = s_small[BR2OFF + c];
                float2 h2v = H22[c * 14 + rp];
                float2 a = acc[j];
                F2[c * 14 + rp] = make_float2(
                    fmaxf(fmaf(-a.x, al, be) + h2v.x, 0.f),
                    fmaxf(fmaf(-a.y, al, be) + h2v.y, 0.f));
            }
        }
        __syncwarp();

        // ---- oa: 5 channel slots x 2 packed elements ----
        {
            float2 acc[5];
            #pragma unroll
            for (int s = 0; s < 5; s++) acc[s] = ZERO2;

            const int slots[5] = {lane, lane + 32, oa2, oa3, oa4};
            const float4* QA = (const float4*)g_qoa;

            #pragma unroll 5
            for (int i4 = 0; i4 < 35; i4++) {
                float2 u0 = F2[4 * i4 + 0];
                float2 u1 = F2[4 * i4 + 1];
                float2 u2 = F2[4 * i4 + 2];
                float2 u3 = F2[4 * i4 + 3];
                const float4* qrow = QA + i4 * 70;
                #pragma unroll
                for (int s = 0; s < 5; s++) {
                    float4 w = __ldg(qrow + slots[s]);
                    acc2(acc[s], u0, w.x);
                    acc2(acc[s], u1, w.y);
                    acc2(acc[s], u2, w.z);
                    acc2(acc[s], u3, w.w);
                }
            }
            __syncwarp();   // F reads done before A overwrite of X region

            const int js[5] = {lane, lane + 32, j2, j3, j4};
            const int ds[5] = {lane, lane + 32, d2, d3, d4};
            #pragma unroll
            for (int s = 0; s < 5; s++) {
                A2[ds[s]] = bnrelu2(acc[s], s_small[AOAOFF + js[s]], s_small[BOAOFF + js[s]]);
            }
            if (lane < 2) {
                A2[70 + lane]  = ZERO2;
                A2[142 + lane] = ZERO2;
            }
        }
        __syncwarp();

        // ---- ob: 2 channel slots x 2 packed elements ----
        {
            float2 b0 = ZERO2;
            float2 b1 = ZERO2;
            const float4* QB = (const float4*)g_qob;
            const float2* a0p = A2 + obb0 * 72;
            const float2* a1p = A2 + 72;

            #pragma unroll 6
            for (int i4 = 0; i4 < 18; i4++) {
                float4 w0 = __ldg(QB + i4 * 30 + ob0);
                acc2(b0, a0p[4 * i4 + 0], w0.x);
                acc2(b0, a0p[4 * i4 + 1], w0.y);
                acc2(b0, a0p[4 * i4 + 2], w0.z);
                acc2(b0, a0p[4 * i4 + 3], w0.w);
                float4 w1 = __ldg(QB + i4 * 30 + ob1);
                acc2(b1, a1p[4 * i4 + 0], w1.x);
                acc2(b1, a1p[4 * i4 + 1], w1.y);
                acc2(b1, a1p[4 * i4 + 2], w1.z);
                acc2(b1, a1p[4 * i4 + 3], w1.w);
            }
            __syncwarp();   // A reads done before B overwrite of H2 region

            B2[obb0 * 32 + obc0] = bnrelu2(b0, s_small[AOBOFF + lane], s_small[BOBOFF + lane]);
            B2[32 + (jb1 - 30)]  = bnrelu2(b1, s_small[AOBOFF + jb1], s_small[BOBOFF + jb1]);
            if (lane < 2) {
                B2[30 + lane] = ZERO2;
                B2[62 + lane] = ZERO2;
            }
        }
        __syncwarp();

        // ---- oc: 4 reductions (2 elems x 2 branches) ----
        {
            float w0 = s_small[QOCOFF + lane], w1 = s_small[QOCOFF + 32 + lane];
            float2 p0 = B2[lane];        // amp branch, 2 elems
            float2 p1 = B2[32 + lane];   // inten branch
            float vA0 = fabsf(fdiff(p0.x, w0)), vA1 = fabsf(fdiff(p0.y, w0));
            float vI0 = fabsf(fdiff(p1.x, w1)), vI1 = fabsf(fdiff(p1.y, w1));
            #pragma unroll
            for (int s = 16; s > 0; s >>= 1) {
                vA0 += __shfl_xor_sync(0xffffffffu, vA0, s);
                vA1 += __shfl_xor_sync(0xffffffffu, vA1, s);
                vI0 += __shfl_xor_sync(0xffffffffu, vI0, s);
                vI1 += __shfl_xor_sync(0xffffffffu, vI1, s);
            }
            if (lane == 0) {
                float aA = s_small[AOCOFF],     bA = s_small[BOCOFF];
                float aI = s_small[AOCOFF + 1], bI = s_small[BOCOFF + 1];
                out[e0]      = fmaxf(fmaf(-vA0, aA, bA), 0.f);
                out[nB + e0] = fmaxf(fmaf(-vI0, aI, bI), 0.f);
                if (e1ok) {
                    out[e1r]      = fmaxf(fmaf(-vA1, aA, bA), 0.f);
                    out[nB + e1r] = fmaxf(fmaf(-vI1, aI, bI), 0.f);
                }
            }
        }
        __syncwarp();   // B reads done before next iteration overwrites
    }
}

// ---------------------------------------------------------------------------
extern "C" void kernel_launch(void* const* d_in, const int* in_sizes, int n_in,
                              void* d_out, int out_size)
{
    const float* x     = (const float*)d_in[0];
    const float* w1    = (const float*)d_in[1];
    const float* bn1   = (const float*)d_in[2];
    const float* w2    = (const float*)d_in[3];
    const float* bn2   = (const float*)d_in[4];
    const float* wr1   = (const float*)d_in[5];
    const float* bnr1  = (const float*)d_in[6];
    const float* wr2   = (const float*)d_in[7];
    const float* bnr2  = (const float*)d_in[8];
    const float* wo1a  = (const float*)d_in[9];
    const float* bno1a = (const float*)d_in[10];
    const float* wo1b  = (const float*)d_in[11];
    const float* bno1b = (const float*)d_in[12];
    const float* wo1c  = (const float*)d_in[13];
    const float* bno1c = (const float*)d_in[14];
    const float* wo2a  = (const float*)d_in[15];
    const float* bno2a = (const float*)d_in[16];
    const float* wo2b  = (const float*)d_in[17];
    const float* bno2b = (const float*)d_in[18];
    const float* wo2c  = (const float*)d_in[19];
    const float* bno2c = (const float*)d_in[20];

    const int nB = in_sizes[0] / 256;
    const int nP = (nB + 1) >> 1;
    const int grid = (nP + 7) / 8 < 512 ? (nP + 7) / 8 : 512;

    setup_kernel<<<11, 256>>>(w1, w2, wr1, wr2, wo1a, wo1b, wo1c, wo2a, wo2b, wo2c,
                              bn1, bn2, bnr1, bnr2, bno1a, bno1b, bno1c,
                              bno2a, bno2b, bno2c);
    taunet_main<<<grid, 256>>>(x, (float*)d_out, nB);
}